// round 1
// baseline (speedup 1.0000x reference)
#include <cuda_runtime.h>
#include <cstdint>

typedef unsigned long long ull;

#define BB  4
#define CC_ 256
#define DD  64
#define NN  4096
#define TI  64
#define TJ  64

// Scratch (no cudaMalloc allowed): q,k in [B][64][N] d-major; v stored TRANSPOSED [B][N][256]
__device__ float g_q[BB*DD*NN];
__device__ float g_k[BB*DD*NN];
__device__ float g_vT[(size_t)BB*NN*CC_];

// ---- packed f32x2 helpers (sm_103a: fma.rn.f32x2 doubles fp32 FMA rate) ----
__device__ __forceinline__ ull pk2(float lo, float hi){
  ull r; asm("mov.b64 %0,{%1,%2};" : "=l"(r) : "f"(lo), "f"(hi)); return r;
}
__device__ __forceinline__ void upk2(ull v, float& lo, float& hi){
  asm("mov.b64 {%0,%1},%2;" : "=f"(lo), "=f"(hi) : "l"(v));
}
__device__ __forceinline__ void ffma2(ull& d, ull a, ull b){
  asm("fma.rn.f32x2 %0,%1,%2,%0;" : "+l"(d) : "l"(a), "l"(b));
}
__device__ __forceinline__ void fmul2(ull& d, ull s){
  asm("mul.rn.f32x2 %0,%0,%1;" : "+l"(d) : "l"(s));
}

// ============================================================================
// Projection: out[b][m][n] = sum_c W[m][c] * x[b][c][n] + bias[m]
// MODE 0 -> g_q, 1 -> g_k (row-major [64][N]); 2 -> g_vT (transposed [N][256])
// Block: 64 m x 128 n tile, 256 threads, thread tile 4m x 8n (f32x2 over n).
// ============================================================================
template<int MODE>
__global__ void __launch_bounds__(256) proj_kernel(
    const float* __restrict__ W, const float* __restrict__ bias,
    const float* __restrict__ x)
{
  __shared__ float Ws[64][17];    // [m][c'] padded
  __shared__ float Xs[16][128];   // [c'][n]

  const int t = threadIdx.x;
  const int b = blockIdx.z;
  const int nbase = blockIdx.x * 128;
  const int mbase = blockIdx.y * 64;
  const float* xb = x + (size_t)b * CC_ * NN;

  ull acc[4][4];
  #pragma unroll
  for (int r = 0; r < 4; r++)
    #pragma unroll
    for (int q = 0; q < 4; q++) acc[r][q] = 0ull;

  const int m0 = (t & 15) * 4;
  const int n0 = (t >> 4) * 8;

  for (int cc = 0; cc < CC_; cc += 16){
    { // stage W chunk [64][16]
      int m = t >> 2, cp = (t & 3) * 4;
      float4 w4 = *(const float4*)(W + (size_t)(mbase + m) * CC_ + cc + cp);
      Ws[m][cp] = w4.x; Ws[m][cp+1] = w4.y; Ws[m][cp+2] = w4.z; Ws[m][cp+3] = w4.w;
    }
    { // stage x chunk [16][128]
      int cp = t >> 4, np = (t & 15) * 8;
      const float* src = xb + (size_t)(cc + cp) * NN + nbase + np;
      *(float4*)&Xs[cp][np]     = *(const float4*)src;
      *(float4*)&Xs[cp][np + 4] = *(const float4*)(src + 4);
    }
    __syncthreads();
    #pragma unroll
    for (int cp = 0; cp < 16; cp++){
      ulonglong2 xa = *(const ulonglong2*)&Xs[cp][n0];
      ulonglong2 xc = *(const ulonglong2*)&Xs[cp][n0 + 4];
      ull xv0 = xa.x, xv1 = xa.y, xv2 = xc.x, xv3 = xc.y;
      #pragma unroll
      for (int r = 0; r < 4; r++){
        float w = Ws[m0 + r][cp];
        ull wb = pk2(w, w);
        ffma2(acc[r][0], wb, xv0); ffma2(acc[r][1], wb, xv1);
        ffma2(acc[r][2], wb, xv2); ffma2(acc[r][3], wb, xv3);
      }
    }
    __syncthreads();
  }

  float av[4][8];
  #pragma unroll
  for (int r = 0; r < 4; r++){
    float bb = bias[mbase + m0 + r];
    #pragma unroll
    for (int q = 0; q < 4; q++){
      float lo, hi; upk2(acc[r][q], lo, hi);
      av[r][2*q]   = lo + bb;
      av[r][2*q+1] = hi + bb;
    }
  }

  if (MODE == 2){
    float* dst = g_vT + (size_t)b * NN * CC_;
    #pragma unroll
    for (int nn = 0; nn < 8; nn++){
      float4 f; f.x = av[0][nn]; f.y = av[1][nn]; f.z = av[2][nn]; f.w = av[3][nn];
      *(float4*)&dst[(size_t)(nbase + n0 + nn) * CC_ + mbase + m0] = f;
    }
  } else {
    float* dst = (MODE == 0 ? g_q : g_k) + (size_t)b * DD * NN;
    #pragma unroll
    for (int r = 0; r < 4; r++){
      *(float4*)&dst[(size_t)(m0 + r) * NN + nbase + n0]     = *(float4*)&av[r][0];
      *(float4*)&dst[(size_t)(m0 + r) * NN + nbase + n0 + 4] = *(float4*)&av[r][4];
    }
  }
}

// ============================================================================
// Fused flash attention + residual epilogue.
// Block = (b, 64-wide i-tile). Loops over all 64 j-tiles of 64.
//   S[j][i] = sum_d q[d][i] k[d][j]   (stored [j][i] in SMEM)
//   online softmax over j; O[c][i] += V[j][c] * P[j][i]
//   out[c][i] = gamma * O/l + x
// 256 threads. PV thread tile 8i x 8c (f32x2 over c). S thread tile 4j x 4i.
// ============================================================================
__global__ void __launch_bounds__(256) attn_kernel(
    const float* __restrict__ x, const float* __restrict__ gamma_p,
    float* __restrict__ out)
{
  extern __shared__ float sm[];
  float* q_s  = sm;               // [64][64]  q_s[d*64+i]
  float* k_s  = q_s + 64*64;      // [64][64]  k_s[d*64+j]
  float* v_s  = k_s + 64*64;      // [64][256] v_s[j*256+c]
  float* Ps   = v_s + 64*256;     // [64][64]  Ps[j*64+i]
  float* red  = Ps + 64*64;       // [4][64]
  float* m_s  = red + 256;        // [64]
  float* l_s  = m_s + 64;         // [64]
  float* sc_s = l_s + 64;         // [64]

  const int t = threadIdx.x;
  const int b = blockIdx.y;
  const int ibase = blockIdx.x * TI;

  const float* qg = g_q  + (size_t)b * DD * NN;
  const float* kg = g_k  + (size_t)b * DD * NN;
  const float* vg = g_vT + (size_t)b * NN * CC_;

  { // load Q tile [64 d][64 i]
    int d = t >> 2, ip = (t & 3) * 16;
    #pragma unroll
    for (int u = 0; u < 4; u++)
      *(float4*)&q_s[d*64 + ip + u*4] = *(const float4*)&qg[(size_t)d*NN + ibase + ip + u*4];
  }
  if (t < 64){ m_s[t] = -1e30f; l_s[t] = 0.f; }

  ull O2[8][4];
  #pragma unroll
  for (int r = 0; r < 8; r++)
    #pragma unroll
    for (int q = 0; q < 4; q++) O2[r][q] = 0ull;

  const int iO = (t & 7) * 8;    // PV: 8 i's
  const int cO = (t >> 3) * 8;   // PV: 8 c's (4 f32x2 pairs)
  const int iS = (t & 15) * 4;   // S: 4 i's
  const int jS = (t >> 4) * 4;   // S: 4 j's
  const int iR = t & 63;         // softmax: i
  const int jG = t >> 6;         // softmax: j-quarter

  for (int jt = 0; jt < NN; jt += TJ){
    __syncthreads();             // previous iteration done reading k_s/v_s
    { // load K tile [64 d][64 j]
      int d = t >> 2, jp = (t & 3) * 16;
      #pragma unroll
      for (int u = 0; u < 4; u++)
        *(float4*)&k_s[d*64 + jp + u*4] = *(const float4*)&kg[(size_t)d*NN + jt + jp + u*4];
    }
    { // load V tile [64 j][256 c] straight from vT (no transpose needed)
      int j = t >> 2, cp = (t & 3) * 64;
      #pragma unroll
      for (int u = 0; u < 16; u++)
        *(float4*)&v_s[j*256 + cp + u*4] = *(const float4*)&vg[(size_t)(jt + j)*CC_ + cp + u*4];
    }
    __syncthreads();

    // ---- S = Q^T K, stored Ps[j][i] ----
    ull s2[4][2];
    #pragma unroll
    for (int r = 0; r < 4; r++){ s2[r][0] = 0ull; s2[r][1] = 0ull; }
    #pragma unroll 8
    for (int d = 0; d < 64; d++){
      float4 q4 = *(const float4*)&q_s[d*64 + iS];
      float4 k4 = *(const float4*)&k_s[d*64 + jS];
      ull qlo = pk2(q4.x, q4.y), qhi = pk2(q4.z, q4.w);
      ull kb0 = pk2(k4.x, k4.x); ffma2(s2[0][0], kb0, qlo); ffma2(s2[0][1], kb0, qhi);
      ull kb1 = pk2(k4.y, k4.y); ffma2(s2[1][0], kb1, qlo); ffma2(s2[1][1], kb1, qhi);
      ull kb2 = pk2(k4.z, k4.z); ffma2(s2[2][0], kb2, qlo); ffma2(s2[2][1], kb2, qhi);
      ull kb3 = pk2(k4.w, k4.w); ffma2(s2[3][0], kb3, qlo); ffma2(s2[3][1], kb3, qhi);
    }
    #pragma unroll
    for (int r = 0; r < 4; r++){
      float4 f;
      upk2(s2[r][0], f.x, f.y); upk2(s2[r][1], f.z, f.w);
      *(float4*)&Ps[(jS + r)*64 + iS] = f;
    }
    __syncthreads();

    // ---- online softmax: partial max ----
    {
      float mx = -1e30f;
      #pragma unroll
      for (int jj = 0; jj < 16; jj++) mx = fmaxf(mx, Ps[(jG*16 + jj)*64 + iR]);
      red[jG*64 + iR] = mx;
    }
    __syncthreads();
    if (t < 64){
      float mx = fmaxf(fmaxf(red[t], red[64 + t]), fmaxf(red[128 + t], red[192 + t]));
      float mo = m_s[t];
      float mn = fmaxf(mo, mx);
      m_s[t]  = mn;
      sc_s[t] = __expf(mo - mn);
    }
    __syncthreads();

    // ---- exponentiate in place + partial sums; rescale O ----
    {
      float mn = m_s[iR];
      float ssum = 0.f;
      #pragma unroll
      for (int jj = 0; jj < 16; jj++){
        int idx = (jG*16 + jj)*64 + iR;
        float p = __expf(Ps[idx] - mn);
        Ps[idx] = p;
        ssum += p;
      }
      red[jG*64 + iR] = ssum;
    }
    #pragma unroll
    for (int r = 0; r < 8; r++){
      float sc = sc_s[iO + r];
      ull sc2 = pk2(sc, sc);
      #pragma unroll
      for (int q = 0; q < 4; q++) fmul2(O2[r][q], sc2);
    }
    __syncthreads();
    if (t < 64)
      l_s[t] = l_s[t]*sc_s[t] + (red[t] + red[64 + t]) + (red[128 + t] + red[192 + t]);

    // ---- O[c][i] += V[j][c] * P[j][i] ----
    #pragma unroll 4
    for (int j = 0; j < 64; j++){
      float4 pa = *(const float4*)&Ps[j*64 + iO];
      float4 pb = *(const float4*)&Ps[j*64 + iO + 4];
      ulonglong2 va = *(const ulonglong2*)&v_s[j*256 + cO];
      ulonglong2 vb = *(const ulonglong2*)&v_s[j*256 + cO + 4];
      ull v0 = va.x, v1 = va.y, v2 = vb.x, v3 = vb.y;
      {ull p2=pk2(pa.x,pa.x); ffma2(O2[0][0],p2,v0); ffma2(O2[0][1],p2,v1); ffma2(O2[0][2],p2,v2); ffma2(O2[0][3],p2,v3);}
      {ull p2=pk2(pa.y,pa.y); ffma2(O2[1][0],p2,v0); ffma2(O2[1][1],p2,v1); ffma2(O2[1][2],p2,v2); ffma2(O2[1][3],p2,v3);}
      {ull p2=pk2(pa.z,pa.z); ffma2(O2[2][0],p2,v0); ffma2(O2[2][1],p2,v1); ffma2(O2[2][2],p2,v2); ffma2(O2[2][3],p2,v3);}
      {ull p2=pk2(pa.w,pa.w); ffma2(O2[3][0],p2,v0); ffma2(O2[3][1],p2,v1); ffma2(O2[3][2],p2,v2); ffma2(O2[3][3],p2,v3);}
      {ull p2=pk2(pb.x,pb.x); ffma2(O2[4][0],p2,v0); ffma2(O2[4][1],p2,v1); ffma2(O2[4][2],p2,v2); ffma2(O2[4][3],p2,v3);}
      {ull p2=pk2(pb.y,pb.y); ffma2(O2[5][0],p2,v0); ffma2(O2[5][1],p2,v1); ffma2(O2[5][2],p2,v2); ffma2(O2[5][3],p2,v3);}
      {ull p2=pk2(pb.z,pb.z); ffma2(O2[6][0],p2,v0); ffma2(O2[6][1],p2,v1); ffma2(O2[6][2],p2,v2); ffma2(O2[6][3],p2,v3);}
      {ull p2=pk2(pb.w,pb.w); ffma2(O2[7][0],p2,v0); ffma2(O2[7][1],p2,v1); ffma2(O2[7][2],p2,v2); ffma2(O2[7][3],p2,v3);}
    }
  }
  __syncthreads();   // final l_s visible

  // ---- epilogue: out = gamma * O / l + x ----
  const float gam = gamma_p[0];
  const float* xg = x   + (size_t)b * CC_ * NN;
  float*       og = out + (size_t)b * CC_ * NN;
  float linv[8];
  #pragma unroll
  for (int r = 0; r < 8; r++) linv[r] = gam / l_s[iO + r];
  float ov[8][8];   // [i][c]
  #pragma unroll
  for (int r = 0; r < 8; r++)
    #pragma unroll
    for (int q = 0; q < 4; q++) upk2(O2[r][q], ov[r][2*q], ov[r][2*q+1]);
  #pragma unroll
  for (int cc = 0; cc < 8; cc++){
    size_t off = (size_t)(cO + cc) * NN + ibase + iO;
    float4 xa = *(const float4*)&xg[off];
    float4 xc = *(const float4*)&xg[off + 4];
    float4 oa, ob;
    oa.x = ov[0][cc]*linv[0] + xa.x;
    oa.y = ov[1][cc]*linv[1] + xa.y;
    oa.z = ov[2][cc]*linv[2] + xa.z;
    oa.w = ov[3][cc]*linv[3] + xa.w;
    ob.x = ov[4][cc]*linv[4] + xc.x;
    ob.y = ov[5][cc]*linv[5] + xc.y;
    ob.z = ov[6][cc]*linv[6] + xc.z;
    ob.w = ov[7][cc]*linv[7] + xc.w;
    *(float4*)&og[off]     = oa;
    *(float4*)&og[off + 4] = ob;
  }
}

// ============================================================================
extern "C" void kernel_launch(void* const* d_in, const int* in_sizes, int n_in,
                              void* d_out, int out_size)
{
  (void)in_sizes; (void)n_in; (void)out_size;
  const float* x  = (const float*)d_in[0];
  const float* Wq = (const float*)d_in[1];
  const float* bq = (const float*)d_in[2];
  const float* Wk = (const float*)d_in[3];
  const float* bk = (const float*)d_in[4];
  const float* Wv = (const float*)d_in[5];
  const float* bv = (const float*)d_in[6];
  const float* gm = (const float*)d_in[7];
  float* out = (float*)d_out;

  const int shmem = (64*64 + 64*64 + 64*256 + 64*64 + 256 + 192) * 4;  // 116480 B
  cudaFuncSetAttribute(attn_kernel, cudaFuncAttributeMaxDynamicSharedMemorySize, shmem);

  proj_kernel<0><<<dim3(NN/128, 1, BB), 256>>>(Wq, bq, x);
  proj_kernel<1><<<dim3(NN/128, 1, BB), 256>>>(Wk, bk, x);
  proj_kernel<2><<<dim3(NN/128, 4, BB), 256>>>(Wv, bv, x);
  attn_kernel<<<dim3(NN/TI, BB), 256, shmem>>>(x, gm, out);
}

// round 3
// speedup vs baseline: 1.0015x; 1.0015x over previous
#include <cuda_runtime.h>
#include <cstdint>

typedef unsigned long long ull;

#define BB  4
#define CC_ 256
#define DD  64
#define NN  4096
#define TI  64
#define TJ  64

// Scratch (no cudaMalloc allowed): q,k in [B][64][N] d-major; v stored TRANSPOSED [B][N][256]
__device__ float g_q[BB*DD*NN];
__device__ float g_k[BB*DD*NN];
__device__ float g_vT[(size_t)BB*NN*CC_];

// ---- packed f32x2 helpers (sm_103a: fma.rn.f32x2 doubles fp32 FMA rate) ----
__device__ __forceinline__ ull pk2(float lo, float hi){
  ull r; asm("mov.b64 %0,{%1,%2};" : "=l"(r) : "f"(lo), "f"(hi)); return r;
}
__device__ __forceinline__ void upk2(ull v, float& lo, float& hi){
  asm("mov.b64 {%0,%1},%2;" : "=f"(lo), "=f"(hi) : "l"(v));
}
__device__ __forceinline__ void ffma2(ull& d, ull a, ull b){
  asm("fma.rn.f32x2 %0,%1,%2,%0;" : "+l"(d) : "l"(a), "l"(b));
}
__device__ __forceinline__ void fmul2(ull& d, ull s){
  asm("mul.rn.f32x2 %0,%0,%1;" : "+l"(d) : "l"(s));
}

// ============================================================================
// Projection: out[b][m][n] = sum_c W[m][c] * x[b][c][n] + bias[m]
// MODE 0 -> g_q, 1 -> g_k (row-major [64][N]); 2 -> g_vT (transposed [N][256])
// Block: 64 m x 128 n tile, 256 threads, thread tile 4m x 8n (f32x2 over n).
// ============================================================================
template<int MODE>
__global__ void __launch_bounds__(256) proj_kernel(
    const float* __restrict__ W, const float* __restrict__ bias,
    const float* __restrict__ x)
{
  __shared__ float Ws[64][17];    // [m][c'] padded
  __shared__ float Xs[16][128];   // [c'][n]

  const int t = threadIdx.x;
  const int b = blockIdx.z;
  const int nbase = blockIdx.x * 128;
  const int mbase = blockIdx.y * 64;
  const float* xb = x + (size_t)b * CC_ * NN;

  ull acc[4][4];
  #pragma unroll
  for (int r = 0; r < 4; r++)
    #pragma unroll
    for (int q = 0; q < 4; q++) acc[r][q] = 0ull;

  const int m0 = (t & 15) * 4;
  const int n0 = (t >> 4) * 8;

  for (int cc = 0; cc < CC_; cc += 16){
    { // stage W chunk [64][16]
      int m = t >> 2, cp = (t & 3) * 4;
      float4 w4 = *(const float4*)(W + (size_t)(mbase + m) * CC_ + cc + cp);
      Ws[m][cp] = w4.x; Ws[m][cp+1] = w4.y; Ws[m][cp+2] = w4.z; Ws[m][cp+3] = w4.w;
    }
    { // stage x chunk [16][128]
      int cp = t >> 4, np = (t & 15) * 8;
      const float* src = xb + (size_t)(cc + cp) * NN + nbase + np;
      *(float4*)&Xs[cp][np]     = *(const float4*)src;
      *(float4*)&Xs[cp][np + 4] = *(const float4*)(src + 4);
    }
    __syncthreads();
    #pragma unroll
    for (int cp = 0; cp < 16; cp++){
      ulonglong2 xa = *(const ulonglong2*)&Xs[cp][n0];
      ulonglong2 xc = *(const ulonglong2*)&Xs[cp][n0 + 4];
      ull xv0 = xa.x, xv1 = xa.y, xv2 = xc.x, xv3 = xc.y;
      #pragma unroll
      for (int r = 0; r < 4; r++){
        float w = Ws[m0 + r][cp];
        ull wb = pk2(w, w);
        ffma2(acc[r][0], wb, xv0); ffma2(acc[r][1], wb, xv1);
        ffma2(acc[r][2], wb, xv2); ffma2(acc[r][3], wb, xv3);
      }
    }
    __syncthreads();
  }

  float av[4][8];
  #pragma unroll
  for (int r = 0; r < 4; r++){
    float bb = bias[mbase + m0 + r];
    #pragma unroll
    for (int q = 0; q < 4; q++){
      float lo, hi; upk2(acc[r][q], lo, hi);
      av[r][2*q]   = lo + bb;
      av[r][2*q+1] = hi + bb;
    }
  }

  if (MODE == 2){
    float* dst = g_vT + (size_t)b * NN * CC_;
    #pragma unroll
    for (int nn = 0; nn < 8; nn++){
      float4 f; f.x = av[0][nn]; f.y = av[1][nn]; f.z = av[2][nn]; f.w = av[3][nn];
      *(float4*)&dst[(size_t)(nbase + n0 + nn) * CC_ + mbase + m0] = f;
    }
  } else {
    float* dst = (MODE == 0 ? g_q : g_k) + (size_t)b * DD * NN;
    #pragma unroll
    for (int r = 0; r < 4; r++){
      *(float4*)&dst[(size_t)(m0 + r) * NN + nbase + n0]     = *(float4*)&av[r][0];
      *(float4*)&dst[(size_t)(m0 + r) * NN + nbase + n0 + 4] = *(float4*)&av[r][4];
    }
  }
}

// ============================================================================
// Fused flash attention + residual epilogue.
// Block = (b, 64-wide i-tile). Loops over all 64 j-tiles of 64.
//   S[j][i] = sum_d q[d][i] k[d][j]   (stored [j][i] in SMEM)
//   online softmax over j; O[c][i] += V[j][c] * P[j][i]
//   out[c][i] = gamma * O/l + x
// 256 threads. PV thread tile 8i x 8c (f32x2 over c). S thread tile 4j x 4i.
// ============================================================================
__global__ void __launch_bounds__(256) attn_kernel(
    const float* __restrict__ x, const float* __restrict__ gamma_p,
    float* __restrict__ out)
{
  extern __shared__ float sm[];
  float* q_s  = sm;               // [64][64]  q_s[d*64+i]
  float* k_s  = q_s + 64*64;      // [64][64]  k_s[d*64+j]
  float* v_s  = k_s + 64*64;      // [64][256] v_s[j*256+c]
  float* Ps   = v_s + 64*256;     // [64][64]  Ps[j*64+i]
  float* red  = Ps + 64*64;       // [4][64]
  float* m_s  = red + 256;        // [64]
  float* l_s  = m_s + 64;         // [64]
  float* sc_s = l_s + 64;         // [64]

  const int t = threadIdx.x;
  const int b = blockIdx.y;
  const int ibase = blockIdx.x * TI;

  const float* qg = g_q  + (size_t)b * DD * NN;
  const float* kg = g_k  + (size_t)b * DD * NN;
  const float* vg = g_vT + (size_t)b * NN * CC_;

  { // load Q tile [64 d][64 i]
    int d = t >> 2, ip = (t & 3) * 16;
    #pragma unroll
    for (int u = 0; u < 4; u++)
      *(float4*)&q_s[d*64 + ip + u*4] = *(const float4*)&qg[(size_t)d*NN + ibase + ip + u*4];
  }
  if (t < 64){ m_s[t] = -1e30f; l_s[t] = 0.f; }

  ull O2[8][4];
  #pragma unroll
  for (int r = 0; r < 8; r++)
    #pragma unroll
    for (int q = 0; q < 4; q++) O2[r][q] = 0ull;

  const int iO = (t & 7) * 8;    // PV: 8 i's
  const int cO = (t >> 3) * 8;   // PV: 8 c's (4 f32x2 pairs)
  const int iS = (t & 15) * 4;   // S: 4 i's
  const int jS = (t >> 4) * 4;   // S: 4 j's
  const int iR = t & 63;         // softmax: i
  const int jG = t >> 6;         // softmax: j-quarter

  for (int jt = 0; jt < NN; jt += TJ){
    __syncthreads();             // previous iteration done reading k_s/v_s
    { // load K tile [64 d][64 j]
      int d = t >> 2, jp = (t & 3) * 16;
      #pragma unroll
      for (int u = 0; u < 4; u++)
        *(float4*)&k_s[d*64 + jp + u*4] = *(const float4*)&kg[(size_t)d*NN + jt + jp + u*4];
    }
    { // load V tile [64 j][256 c] straight from vT (no transpose needed)
      int j = t >> 2, cp = (t & 3) * 64;
      #pragma unroll
      for (int u = 0; u < 16; u++)
        *(float4*)&v_s[j*256 + cp + u*4] = *(const float4*)&vg[(size_t)(jt + j)*CC_ + cp + u*4];
    }
    __syncthreads();

    // ---- S = Q^T K, stored Ps[j][i] ----
    ull s2[4][2];
    #pragma unroll
    for (int r = 0; r < 4; r++){ s2[r][0] = 0ull; s2[r][1] = 0ull; }
    #pragma unroll 8
    for (int d = 0; d < 64; d++){
      float4 q4 = *(const float4*)&q_s[d*64 + iS];
      float4 k4 = *(const float4*)&k_s[d*64 + jS];
      ull qlo = pk2(q4.x, q4.y), qhi = pk2(q4.z, q4.w);
      ull kb0 = pk2(k4.x, k4.x); ffma2(s2[0][0], kb0, qlo); ffma2(s2[0][1], kb0, qhi);
      ull kb1 = pk2(k4.y, k4.y); ffma2(s2[1][0], kb1, qlo); ffma2(s2[1][1], kb1, qhi);
      ull kb2 = pk2(k4.z, k4.z); ffma2(s2[2][0], kb2, qlo); ffma2(s2[2][1], kb2, qhi);
      ull kb3 = pk2(k4.w, k4.w); ffma2(s2[3][0], kb3, qlo); ffma2(s2[3][1], kb3, qhi);
    }
    #pragma unroll
    for (int r = 0; r < 4; r++){
      float4 f;
      upk2(s2[r][0], f.x, f.y); upk2(s2[r][1], f.z, f.w);
      *(float4*)&Ps[(jS + r)*64 + iS] = f;
    }
    __syncthreads();

    // ---- online softmax: partial max ----
    {
      float mx = -1e30f;
      #pragma unroll
      for (int jj = 0; jj < 16; jj++) mx = fmaxf(mx, Ps[(jG*16 + jj)*64 + iR]);
      red[jG*64 + iR] = mx;
    }
    __syncthreads();
    if (t < 64){
      float mx = fmaxf(fmaxf(red[t], red[64 + t]), fmaxf(red[128 + t], red[192 + t]));
      float mo = m_s[t];
      float mn = fmaxf(mo, mx);
      m_s[t]  = mn;
      sc_s[t] = __expf(mo - mn);
    }
    __syncthreads();

    // ---- exponentiate in place + partial sums; rescale O ----
    {
      float mn = m_s[iR];
      float ssum = 0.f;
      #pragma unroll
      for (int jj = 0; jj < 16; jj++){
        int idx = (jG*16 + jj)*64 + iR;
        float p = __expf(Ps[idx] - mn);
        Ps[idx] = p;
        ssum += p;
      }
      red[jG*64 + iR] = ssum;
    }
    #pragma unroll
    for (int r = 0; r < 8; r++){
      float sc = sc_s[iO + r];
      ull sc2 = pk2(sc, sc);
      #pragma unroll
      for (int q = 0; q < 4; q++) fmul2(O2[r][q], sc2);
    }
    __syncthreads();
    if (t < 64)
      l_s[t] = l_s[t]*sc_s[t] + (red[t] + red[64 + t]) + (red[128 + t] + red[192 + t]);

    // ---- O[c][i] += V[j][c] * P[j][i] ----
    #pragma unroll 4
    for (int j = 0; j < 64; j++){
      float4 pa = *(const float4*)&Ps[j*64 + iO];
      float4 pb = *(const float4*)&Ps[j*64 + iO + 4];
      ulonglong2 va = *(const ulonglong2*)&v_s[j*256 + cO];
      ulonglong2 vb = *(const ulonglong2*)&v_s[j*256 + cO + 4];
      ull v0 = va.x, v1 = va.y, v2 = vb.x, v3 = vb.y;
      {ull p2=pk2(pa.x,pa.x); ffma2(O2[0][0],p2,v0); ffma2(O2[0][1],p2,v1); ffma2(O2[0][2],p2,v2); ffma2(O2[0][3],p2,v3);}
      {ull p2=pk2(pa.y,pa.y); ffma2(O2[1][0],p2,v0); ffma2(O2[1][1],p2,v1); ffma2(O2[1][2],p2,v2); ffma2(O2[1][3],p2,v3);}
      {ull p2=pk2(pa.z,pa.z); ffma2(O2[2][0],p2,v0); ffma2(O2[2][1],p2,v1); ffma2(O2[2][2],p2,v2); ffma2(O2[2][3],p2,v3);}
      {ull p2=pk2(pa.w,pa.w); ffma2(O2[3][0],p2,v0); ffma2(O2[3][1],p2,v1); ffma2(O2[3][2],p2,v2); ffma2(O2[3][3],p2,v3);}
      {ull p2=pk2(pb.x,pb.x); ffma2(O2[4][0],p2,v0); ffma2(O2[4][1],p2,v1); ffma2(O2[4][2],p2,v2); ffma2(O2[4][3],p2,v3);}
      {ull p2=pk2(pb.y,pb.y); ffma2(O2[5][0],p2,v0); ffma2(O2[5][1],p2,v1); ffma2(O2[5][2],p2,v2); ffma2(O2[5][3],p2,v3);}
      {ull p2=pk2(pb.z,pb.z); ffma2(O2[6][0],p2,v0); ffma2(O2[6][1],p2,v1); ffma2(O2[6][2],p2,v2); ffma2(O2[6][3],p2,v3);}
      {ull p2=pk2(pb.w,pb.w); ffma2(O2[7][0],p2,v0); ffma2(O2[7][1],p2,v1); ffma2(O2[7][2],p2,v2); ffma2(O2[7][3],p2,v3);}
    }
  }
  __syncthreads();   // final l_s visible

  // ---- epilogue: out = gamma * O / l + x ----
  const float gam = gamma_p[0];
  const float* xg = x   + (size_t)b * CC_ * NN;
  float*       og = out + (size_t)b * CC_ * NN;
  float linv[8];
  #pragma unroll
  for (int r = 0; r < 8; r++) linv[r] = gam / l_s[iO + r];
  float ov[8][8];   // [i][c]
  #pragma unroll
  for (int r = 0; r < 8; r++)
    #pragma unroll
    for (int q = 0; q < 4; q++) upk2(O2[r][q], ov[r][2*q], ov[r][2*q+1]);
  #pragma unroll
  for (int cc = 0; cc < 8; cc++){
    size_t off = (size_t)(cO + cc) * NN + ibase + iO;
    float4 xa = *(const float4*)&xg[off];
    float4 xc = *(const float4*)&xg[off + 4];
    float4 oa, ob;
    oa.x = ov[0][cc]*linv[0] + xa.x;
    oa.y = ov[1][cc]*linv[1] + xa.y;
    oa.z = ov[2][cc]*linv[2] + xa.z;
    oa.w = ov[3][cc]*linv[3] + xa.w;
    ob.x = ov[4][cc]*linv[4] + xc.x;
    ob.y = ov[5][cc]*linv[5] + xc.y;
    ob.z = ov[6][cc]*linv[6] + xc.z;
    ob.w = ov[7][cc]*linv[7] + xc.w;
    *(float4*)&og[off]     = oa;
    *(float4*)&og[off + 4] = ob;
  }
}

// ============================================================================
extern "C" void kernel_launch(void* const* d_in, const int* in_sizes, int n_in,
                              void* d_out, int out_size)
{
  (void)in_sizes; (void)n_in; (void)out_size;
  const float* x  = (const float*)d_in[0];
  const float* Wq = (const float*)d_in[1];
  const float* bq = (const float*)d_in[2];
  const float* Wk = (const float*)d_in[3];
  const float* bk = (const float*)d_in[4];
  const float* Wv = (const float*)d_in[5];
  const float* bv = (const float*)d_in[6];
  const float* gm = (const float*)d_in[7];
  float* out = (float*)d_out;

  const int shmem = (64*64 + 64*64 + 64*256 + 64*64 + 256 + 192) * 4;  // 116480 B
  cudaFuncSetAttribute(attn_kernel, cudaFuncAttributeMaxDynamicSharedMemorySize, shmem);

  proj_kernel<0><<<dim3(NN/128, 1, BB), 256>>>(Wq, bq, x);
  proj_kernel<1><<<dim3(NN/128, 1, BB), 256>>>(Wk, bk, x);
  proj_kernel<2><<<dim3(NN/128, 4, BB), 256>>>(Wv, bv, x);
  attn_kernel<<<dim3(NN/TI, BB), 256, shmem>>>(x, gm, out);
}

// round 5
// speedup vs baseline: 1.0074x; 1.0060x over previous
#include <cuda_runtime.h>
#include <cstdint>

typedef unsigned long long ull;

#define BB  4
#define CC_ 256
#define DD  64
#define NN  4096
#define TI  64
#define TJ  64

// Scratch (no cudaMalloc allowed): q,k in [B][64][N] d-major; v stored TRANSPOSED [B][N][256]
__device__ float g_q[BB*DD*NN];
__device__ float g_k[BB*DD*NN];
__device__ float g_vT[(size_t)BB*NN*CC_];

// ---- packed f32x2 helpers (sm_103a: fma.rn.f32x2 doubles fp32 FMA rate) ----
__device__ __forceinline__ ull pk2(float lo, float hi){
  ull r; asm("mov.b64 %0,{%1,%2};" : "=l"(r) : "f"(lo), "f"(hi)); return r;
}
__device__ __forceinline__ void upk2(ull v, float& lo, float& hi){
  asm("mov.b64 {%0,%1},%2;" : "=f"(lo), "=f"(hi) : "l"(v));
}
__device__ __forceinline__ void ffma2(ull& d, ull a, ull b){
  asm("fma.rn.f32x2 %0,%1,%2,%0;" : "+l"(d) : "l"(a), "l"(b));
}
__device__ __forceinline__ void fmul2(ull& d, ull s){
  asm("mul.rn.f32x2 %0,%0,%1;" : "+l"(d) : "l"(s));
}

// ============================================================================
// Projection: out[b][m][n] = sum_c W[m][c] * x[b][c][n] + bias[m]
// MODE 0 -> g_q, 1 -> g_k (row-major [64][N]); 2 -> g_vT (transposed [N][256])
// ============================================================================
template<int MODE>
__global__ void __launch_bounds__(256) proj_kernel(
    const float* __restrict__ W, const float* __restrict__ bias,
    const float* __restrict__ x)
{
  __shared__ float Ws[64][17];    // [m][c'] padded
  __shared__ float Xs[16][128];   // [c'][n]

  const int t = threadIdx.x;
  const int b = blockIdx.z;
  const int nbase = blockIdx.x * 128;
  const int mbase = blockIdx.y * 64;
  const float* xb = x + (size_t)b * CC_ * NN;

  ull acc[4][4];
  #pragma unroll
  for (int r = 0; r < 4; r++)
    #pragma unroll
    for (int q = 0; q < 4; q++) acc[r][q] = 0ull;

  const int m0 = (t & 15) * 4;
  const int n0 = (t >> 4) * 8;

  for (int cc = 0; cc < CC_; cc += 16){
    {
      int m = t >> 2, cp = (t & 3) * 4;
      float4 w4 = *(const float4*)(W + (size_t)(mbase + m) * CC_ + cc + cp);
      Ws[m][cp] = w4.x; Ws[m][cp+1] = w4.y; Ws[m][cp+2] = w4.z; Ws[m][cp+3] = w4.w;
    }
    {
      int cp = t >> 4, np = (t & 15) * 8;
      const float* src = xb + (size_t)(cc + cp) * NN + nbase + np;
      *(float4*)&Xs[cp][np]     = *(const float4*)src;
      *(float4*)&Xs[cp][np + 4] = *(const float4*)(src + 4);
    }
    __syncthreads();
    #pragma unroll
    for (int cp = 0; cp < 16; cp++){
      ulonglong2 xa = *(const ulonglong2*)&Xs[cp][n0];
      ulonglong2 xc = *(const ulonglong2*)&Xs[cp][n0 + 4];
      ull xv0 = xa.x, xv1 = xa.y, xv2 = xc.x, xv3 = xc.y;
      #pragma unroll
      for (int r = 0; r < 4; r++){
        float w = Ws[m0 + r][cp];
        ull wb = pk2(w, w);
        ffma2(acc[r][0], wb, xv0); ffma2(acc[r][1], wb, xv1);
        ffma2(acc[r][2], wb, xv2); ffma2(acc[r][3], wb, xv3);
      }
    }
    __syncthreads();
  }

  float av[4][8];
  #pragma unroll
  for (int r = 0; r < 4; r++){
    float bb = bias[mbase + m0 + r];
    #pragma unroll
    for (int q = 0; q < 4; q++){
      float lo, hi; upk2(acc[r][q], lo, hi);
      av[r][2*q]   = lo + bb;
      av[r][2*q+1] = hi + bb;
    }
  }

  if (MODE == 2){
    float* dst = g_vT + (size_t)b * NN * CC_;
    #pragma unroll
    for (int nn = 0; nn < 8; nn++){
      float4 f; f.x = av[0][nn]; f.y = av[1][nn]; f.z = av[2][nn]; f.w = av[3][nn];
      *(float4*)&dst[(size_t)(nbase + n0 + nn) * CC_ + mbase + m0] = f;
    }
  } else {
    float* dst = (MODE == 0 ? g_q : g_k) + (size_t)b * DD * NN;
    #pragma unroll
    for (int r = 0; r < 4; r++){
      *(float4*)&dst[(size_t)(m0 + r) * NN + nbase + n0]     = *(float4*)&av[r][0];
      *(float4*)&dst[(size_t)(m0 + r) * NN + nbase + n0 + 4] = *(float4*)&av[r][4];
    }
  }
}

// ============================================================================
// Fused flash attention + residual epilogue.
// Identical structure to R1, but __launch_bounds__(256, 2): caps regs at 128
// so TWO CTAs fit per SM (2 x 116480 B smem = 232960 <= 233472). 16 warps/SM
// hide LDS->FFMA latency that capped issue at 28%.
// ============================================================================
__global__ void __launch_bounds__(256, 2) attn_kernel(
    const float* __restrict__ x, const float* __restrict__ gamma_p,
    float* __restrict__ out)
{
  extern __shared__ float sm[];
  float* q_s  = sm;               // [64][64]  q_s[d*64+i]
  float* k_s  = q_s + 64*64;      // [64][64]  k_s[d*64+j]
  float* v_s  = k_s + 64*64;      // [64][256] v_s[j*256+c]
  float* Ps   = v_s + 64*256;     // [64][64]  Ps[j*64+i]
  float* red  = Ps + 64*64;       // [4][64]
  float* m_s  = red + 256;        // [64]
  float* l_s  = m_s + 64;         // [64]
  float* sc_s = l_s + 64;         // [64]

  const int t = threadIdx.x;
  const int b = blockIdx.y;
  const int ibase = blockIdx.x * TI;

  const float* qg = g_q  + (size_t)b * DD * NN;
  const float* kg = g_k  + (size_t)b * DD * NN;
  const float* vg = g_vT + (size_t)b * NN * CC_;

  { // load Q tile [64 d][64 i]
    int d = t >> 2, ip = (t & 3) * 16;
    #pragma unroll
    for (int u = 0; u < 4; u++)
      *(float4*)&q_s[d*64 + ip + u*4] = *(const float4*)&qg[(size_t)d*NN + ibase + ip + u*4];
  }
  if (t < 64){ m_s[t] = -1e30f; l_s[t] = 0.f; }

  ull O2[8][4];
  #pragma unroll
  for (int r = 0; r < 8; r++)
    #pragma unroll
    for (int q = 0; q < 4; q++) O2[r][q] = 0ull;

  const int iO = (t & 7) * 8;    // PV: 8 i's
  const int cO = (t >> 3) * 8;   // PV: 8 c's (4 f32x2 pairs)
  const int iS = (t & 15) * 4;   // S: 4 i's
  const int jS = (t >> 4) * 4;   // S: 4 j's
  const int iR = t & 63;         // softmax: i
  const int jG = t >> 6;         // softmax: j-quarter

  for (int jt = 0; jt < NN; jt += TJ){
    __syncthreads();             // previous iteration done reading k_s/v_s
    { // load K tile [64 d][64 j]
      int d = t >> 2, jp = (t & 3) * 16;
      #pragma unroll
      for (int u = 0; u < 4; u++)
        *(float4*)&k_s[d*64 + jp + u*4] = *(const float4*)&kg[(size_t)d*NN + jt + jp + u*4];
    }
    { // load V tile [64 j][256 c] straight from vT (no transpose needed)
      int j = t >> 2, cp = (t & 3) * 64;
      #pragma unroll
      for (int u = 0; u < 16; u++)
        *(float4*)&v_s[j*256 + cp + u*4] = *(const float4*)&vg[(size_t)(jt + j)*CC_ + cp + u*4];
    }
    __syncthreads();

    // ---- S = Q^T K, stored Ps[j][i] ----
    ull s2[4][2];
    #pragma unroll
    for (int r = 0; r < 4; r++){ s2[r][0] = 0ull; s2[r][1] = 0ull; }
    #pragma unroll 8
    for (int d = 0; d < 64; d++){
      float4 q4 = *(const float4*)&q_s[d*64 + iS];
      float4 k4 = *(const float4*)&k_s[d*64 + jS];
      ull qlo = pk2(q4.x, q4.y), qhi = pk2(q4.z, q4.w);
      ull kb0 = pk2(k4.x, k4.x); ffma2(s2[0][0], kb0, qlo); ffma2(s2[0][1], kb0, qhi);
      ull kb1 = pk2(k4.y, k4.y); ffma2(s2[1][0], kb1, qlo); ffma2(s2[1][1], kb1, qhi);
      ull kb2 = pk2(k4.z, k4.z); ffma2(s2[2][0], kb2, qlo); ffma2(s2[2][1], kb2, qhi);
      ull kb3 = pk2(k4.w, k4.w); ffma2(s2[3][0], kb3, qlo); ffma2(s2[3][1], kb3, qhi);
    }
    #pragma unroll
    for (int r = 0; r < 4; r++){
      float4 f;
      upk2(s2[r][0], f.x, f.y); upk2(s2[r][1], f.z, f.w);
      *(float4*)&Ps[(jS + r)*64 + iS] = f;
    }
    __syncthreads();

    // ---- online softmax: partial max ----
    {
      float mx = -1e30f;
      #pragma unroll
      for (int jj = 0; jj < 16; jj++) mx = fmaxf(mx, Ps[(jG*16 + jj)*64 + iR]);
      red[jG*64 + iR] = mx;
    }
    __syncthreads();
    if (t < 64){
      float mx = fmaxf(fmaxf(red[t], red[64 + t]), fmaxf(red[128 + t], red[192 + t]));
      float mo = m_s[t];
      float mn = fmaxf(mo, mx);
      m_s[t]  = mn;
      sc_s[t] = __expf(mo - mn);
    }
    __syncthreads();

    // ---- exponentiate in place + partial sums; rescale O ----
    {
      float mn = m_s[iR];
      float ssum = 0.f;
      #pragma unroll
      for (int jj = 0; jj < 16; jj++){
        int idx = (jG*16 + jj)*64 + iR;
        float p = __expf(Ps[idx] - mn);
        Ps[idx] = p;
        ssum += p;
      }
      red[jG*64 + iR] = ssum;
    }
    #pragma unroll
    for (int r = 0; r < 8; r++){
      float sc = sc_s[iO + r];
      ull sc2 = pk2(sc, sc);
      #pragma unroll
      for (int q = 0; q < 4; q++) fmul2(O2[r][q], sc2);
    }
    __syncthreads();
    if (t < 64)
      l_s[t] = l_s[t]*sc_s[t] + (red[t] + red[64 + t]) + (red[128 + t] + red[192 + t]);

    // ---- O[c][i] += V[j][c] * P[j][i] ----
    #pragma unroll 4
    for (int j = 0; j < 64; j++){
      float4 pa = *(const float4*)&Ps[j*64 + iO];
      float4 pb = *(const float4*)&Ps[j*64 + iO + 4];
      ulonglong2 va = *(const ulonglong2*)&v_s[j*256 + cO];
      ulonglong2 vb = *(const ulonglong2*)&v_s[j*256 + cO + 4];
      ull v0 = va.x, v1 = va.y, v2 = vb.x, v3 = vb.y;
      {ull p2=pk2(pa.x,pa.x); ffma2(O2[0][0],p2,v0); ffma2(O2[0][1],p2,v1); ffma2(O2[0][2],p2,v2); ffma2(O2[0][3],p2,v3);}
      {ull p2=pk2(pa.y,pa.y); ffma2(O2[1][0],p2,v0); ffma2(O2[1][1],p2,v1); ffma2(O2[1][2],p2,v2); ffma2(O2[1][3],p2,v3);}
      {ull p2=pk2(pa.z,pa.z); ffma2(O2[2][0],p2,v0); ffma2(O2[2][1],p2,v1); ffma2(O2[2][2],p2,v2); ffma2(O2[2][3],p2,v3);}
      {ull p2=pk2(pa.w,pa.w); ffma2(O2[3][0],p2,v0); ffma2(O2[3][1],p2,v1); ffma2(O2[3][2],p2,v2); ffma2(O2[3][3],p2,v3);}
      {ull p2=pk2(pb.x,pb.x); ffma2(O2[4][0],p2,v0); ffma2(O2[4][1],p2,v1); ffma2(O2[4][2],p2,v2); ffma2(O2[4][3],p2,v3);}
      {ull p2=pk2(pb.y,pb.y); ffma2(O2[5][0],p2,v0); ffma2(O2[5][1],p2,v1); ffma2(O2[5][2],p2,v2); ffma2(O2[5][3],p2,v3);}
      {ull p2=pk2(pb.z,pb.z); ffma2(O2[6][0],p2,v0); ffma2(O2[6][1],p2,v1); ffma2(O2[6][2],p2,v2); ffma2(O2[6][3],p2,v3);}
      {ull p2=pk2(pb.w,pb.w); ffma2(O2[7][0],p2,v0); ffma2(O2[7][1],p2,v1); ffma2(O2[7][2],p2,v2); ffma2(O2[7][3],p2,v3);}
    }
  }
  __syncthreads();   // final l_s visible

  // ---- epilogue: out = gamma * O / l + x ----
  const float gam = gamma_p[0];
  const float* xg = x   + (size_t)b * CC_ * NN;
  float*       og = out + (size_t)b * CC_ * NN;
  float linv[8];
  #pragma unroll
  for (int r = 0; r < 8; r++) linv[r] = gam / l_s[iO + r];
  float ov[8][8];   // [i][c]
  #pragma unroll
  for (int r = 0; r < 8; r++)
    #pragma unroll
    for (int q = 0; q < 4; q++) upk2(O2[r][q], ov[r][2*q], ov[r][2*q+1]);
  #pragma unroll
  for (int cc = 0; cc < 8; cc++){
    size_t off = (size_t)(cO + cc) * NN + ibase + iO;
    float4 xa = *(const float4*)&xg[off];
    float4 xc = *(const float4*)&xg[off + 4];
    float4 oa, ob;
    oa.x = ov[0][cc]*linv[0] + xa.x;
    oa.y = ov[1][cc]*linv[1] + xa.y;
    oa.z = ov[2][cc]*linv[2] + xa.z;
    oa.w = ov[3][cc]*linv[3] + xa.w;
    ob.x = ov[4][cc]*linv[4] + xc.x;
    ob.y = ov[5][cc]*linv[5] + xc.y;
    ob.z = ov[6][cc]*linv[6] + xc.z;
    ob.w = ov[7][cc]*linv[7] + xc.w;
    *(float4*)&og[off]     = oa;
    *(float4*)&og[off + 4] = ob;
  }
}

// ============================================================================
extern "C" void kernel_launch(void* const* d_in, const int* in_sizes, int n_in,
                              void* d_out, int out_size)
{
  (void)in_sizes; (void)n_in; (void)out_size;
  const float* x  = (const float*)d_in[0];
  const float* Wq = (const float*)d_in[1];
  const float* bq = (const float*)d_in[2];
  const float* Wk = (const float*)d_in[3];
  const float* bk = (const float*)d_in[4];
  const float* Wv = (const float*)d_in[5];
  const float* bv = (const float*)d_in[6];
  const float* gm = (const float*)d_in[7];
  float* out = (float*)d_out;

  const int shmem = (64*64 + 64*64 + 64*256 + 64*64 + 256 + 192) * 4;  // 116480 B
  cudaFuncSetAttribute(attn_kernel, cudaFuncAttributeMaxDynamicSharedMemorySize, shmem);

  proj_kernel<0><<<dim3(NN/128, 1, BB), 256>>>(Wq, bq, x);
  proj_kernel<1><<<dim3(NN/128, 1, BB), 256>>>(Wk, bk, x);
  proj_kernel<2><<<dim3(NN/128, 4, BB), 256>>>(Wv, bv, x);
  attn_kernel<<<dim3(NN/TI, BB), 256, shmem>>>(x, gm, out);
}